// round 7
// baseline (speedup 1.0000x reference)
#include <cuda_runtime.h>
#include <math.h>

// ---------------------------------------------------------------------------
// Radon backprojection:
//   K1: transpose sino[B,A,P] -> sino_t[A,P,B] (+trig table float4, +zero out)
//   K2: 4-way grid-level angle split; each thread handles TWO pixels
//       (y and y+N/2, same x) -> 4 independent LDG.128 in flight per iter,
//       trig/loop overhead amortized. RED.ADD epilogue into zeroed output.
// ---------------------------------------------------------------------------

#define MAX_A 2048
#define MAX_ELEMS (8 * 1024 * 1024)
#define PIX_PER_BLK 448
#define NSPLIT 4

__device__ float4 g_trig[MAX_A];        // (cos/dp, sin/dp, (N/2)*sin/dp, 0)
__device__ float  g_c0;                 // -p0/dp
__device__ float  g_sino_t[MAX_ELEMS];  // [a][p][b], b innermost

// K1: transpose + trig table + output zero-init, fused.
__global__ void radon_prep_transpose4_kernel(const float* __restrict__ sino,
                                             const float* __restrict__ thetas,
                                             const float* __restrict__ positions,
                                             float4* __restrict__ out4,
                                             int A, int P, int N, int NOUT4)
{
    int idx = blockIdx.x * blockDim.x + threadIdx.x;
    int AP = A * P;

    float p0  = positions[0];
    float dp  = positions[1] - positions[0];
    float inv = 1.0f / dp;

    if (idx < A) {
        float s, c;
        sincosf(thetas[idx], &s, &c);
        float si = s * inv;
        g_trig[idx] = make_float4(c * inv, si, (float)(N >> 1) * si, 0.f);
    }
    if (idx == 0) g_c0 = -p0 * inv;

    if (idx < AP) {
        float4 v;
        v.x = __ldg(sino + idx);
        v.y = __ldg(sino + idx + AP);
        v.z = __ldg(sino + idx + 2 * AP);
        v.w = __ldg(sino + idx + 3 * AP);
        ((float4*)g_sino_t)[idx] = v;
    }
    if (idx < NOUT4)
        out4[idx] = make_float4(0.f, 0.f, 0.f, 0.f);
}

__global__ void radon_prep_transpose_kernel(const float* __restrict__ sino,
                                            const float* __restrict__ thetas,
                                            const float* __restrict__ positions,
                                            int BC, int A, int P)
{
    int idx = blockIdx.x * blockDim.x + threadIdx.x;
    int AP = A * P;

    float p0  = positions[0];
    float dp  = positions[1] - positions[0];
    float inv = 1.0f / dp;

    if (idx < A) {
        float s, c;
        sincosf(thetas[idx], &s, &c);
        g_trig[idx] = make_float4(c * inv, s * inv, 0.f, 0.f);
    }
    if (idx == 0) g_c0 = -p0 * inv;

    if (idx < AP) {
        for (int b = 0; b < BC; ++b)
            g_sino_t[idx * BC + b] = __ldg(sino + idx + b * AP);
    }
}

// K2 (BC==4): 2 pixels per thread (rows y and y+N/2), 4-way angle split.
__global__ void __launch_bounds__(PIX_PER_BLK, 2)
radon_backproj4_kernel(float* __restrict__ out, int A, int P, int N, int NN)
{
    __shared__ float4 strig[512];
    for (int i = threadIdx.x; i < A; i += blockDim.x) strig[i] = g_trig[i];
    __syncthreads();

    int HALF_NN = NN >> 1;
    int h   = blockIdx.x % NSPLIT;
    int idx = (blockIdx.x / NSPLIT) * PIX_PER_BLK + threadIdx.x;
    if (idx >= HALF_NN) return;

    int x = idx % N;
    int y = idx / N;
    float half = 0.5f * (float)(N - 1);
    float cx = (float)x - half;
    float cy = half - (float)y;
    float c0 = g_c0;
    int   Pm2 = P - 2;

    int chunk = (A + NSPLIT - 1) / NSPLIT;
    int a_lo  = h * chunk;
    int a_hi  = min(A, a_lo + chunk);

    float4 acc1 = make_float4(0.f, 0.f, 0.f, 0.f);
    float4 acc2 = make_float4(0.f, 0.f, 0.f, 0.f);
    const float4* __restrict__ sino = (const float4*)g_sino_t;

    #pragma unroll 2
    for (int a = a_lo; a < a_hi; ++a) {
        float4 tr = strig[a];
        const float4* row = sino + a * P;

        // pixel 1: (x, y)
        float f1  = fmaf(cx, tr.x, fmaf(cy, tr.y, c0));
        float fi1 = floorf(f1);
        int   i1  = min(max((int)fi1, 0), Pm2);
        float4 v10 = __ldg(row + i1);
        float4 v11 = __ldg(row + i1 + 1);

        // pixel 2: (x, y + N/2) -> f2 = f1 - (N/2)*sin/dp
        float f2  = f1 - tr.z;
        float fi2 = floorf(f2);
        int   i2  = min(max((int)fi2, 0), Pm2);
        float4 v20 = __ldg(row + i2);
        float4 v21 = __ldg(row + i2 + 1);

        float w11 = f1 - fi1, w10 = 1.0f - w11;
        float w21 = f2 - fi2, w20 = 1.0f - w21;

        acc1.x = fmaf(v10.x, w10, fmaf(v11.x, w11, acc1.x));
        acc1.y = fmaf(v10.y, w10, fmaf(v11.y, w11, acc1.y));
        acc1.z = fmaf(v10.z, w10, fmaf(v11.z, w11, acc1.z));
        acc1.w = fmaf(v10.w, w10, fmaf(v11.w, w11, acc1.w));

        acc2.x = fmaf(v20.x, w20, fmaf(v21.x, w21, acc2.x));
        acc2.y = fmaf(v20.y, w20, fmaf(v21.y, w21, acc2.y));
        acc2.z = fmaf(v20.z, w20, fmaf(v21.z, w21, acc2.z));
        acc2.w = fmaf(v20.w, w20, fmaf(v21.w, w21, acc2.w));
    }

    int idx2 = idx + HALF_NN;
    atomicAdd(out + idx,           acc1.x);
    atomicAdd(out + idx + NN,      acc1.y);
    atomicAdd(out + idx + 2 * NN,  acc1.z);
    atomicAdd(out + idx + 3 * NN,  acc1.w);
    atomicAdd(out + idx2,          acc2.x);
    atomicAdd(out + idx2 + NN,     acc2.y);
    atomicAdd(out + idx2 + 2 * NN, acc2.z);
    atomicAdd(out + idx2 + 3 * NN, acc2.w);
}

// K2 generic BC fallback (single pass, no atomics, keeps validity predicate).
__global__ void radon_backproj_generic_kernel(float* __restrict__ out,
                                              int BC, int A, int P, int N, int NN)
{
    __shared__ float2 strig[MAX_A];
    for (int i = threadIdx.x; i < A; i += blockDim.x) {
        float4 t = g_trig[i];
        strig[i] = make_float2(t.x, t.y);
    }
    __syncthreads();

    int idx = blockIdx.x * blockDim.x + threadIdx.x;
    if (idx >= NN) return;

    int x = idx % N;
    int y = idx / N;
    float half = 0.5f * (float)(N - 1);
    float cx = (float)x - half;
    float cy = half - (float)y;
    float c0 = g_c0;
    int   Pm2 = P - 2;

    for (int b = 0; b < BC; ++b) {
        float acc = 0.f;
        for (int a = 0; a < A; ++a) {
            float2 tr = strig[a];
            float f  = fmaf(cx, tr.x, fmaf(cy, tr.y, c0));
            float fi = floorf(f);
            int   i0 = (int)fi;
            bool  valid = (i0 >= 0) && (i0 <= Pm2);
            int   i0c = min(max(i0, 0), Pm2);
            float v0 = g_sino_t[(a * P + i0c) * BC + b];
            float v1 = g_sino_t[(a * P + i0c + 1) * BC + b];
            float w  = f - fi;
            float w1 = valid ? w       : 0.f;
            float w0 = valid ? 1.f - w : 0.f;
            acc = fmaf(v0, w0, fmaf(v1, w1, acc));
        }
        out[b * NN + idx] = acc;
    }
}

extern "C" void kernel_launch(void* const* d_in, const int* in_sizes, int n_in,
                              void* d_out, int out_size)
{
    const float* sino      = (const float*)d_in[0];
    const float* thetas    = (const float*)d_in[1];
    const float* positions = (const float*)d_in[2];

    int A  = in_sizes[1];
    int P  = in_sizes[2];
    int BC = in_sizes[0] / (A * P);
    int N  = (int)(sqrt((double)(out_size / BC)) + 0.5);
    int NN = N * N;
    float* out = (float*)d_out;

    int AP = A * P;
    if (BC == 4 && (N & 1) == 0 && A <= 512) {
        int NOUT4 = NN;                                  // out has 4*NN floats
        int prep_elems = AP > NOUT4 ? AP : NOUT4;
        radon_prep_transpose4_kernel<<<(prep_elems + 255) / 256, 256>>>(
            sino, thetas, positions, (float4*)out, A, P, N, NOUT4);

        int half_nn = NN >> 1;
        int stripes = (half_nn + PIX_PER_BLK - 1) / PIX_PER_BLK;  // 74 for N=256
        radon_backproj4_kernel<<<NSPLIT * stripes, PIX_PER_BLK>>>(out, A, P, N, NN);
    } else {
        radon_prep_transpose_kernel<<<(AP + 255) / 256, 256>>>(sino, thetas, positions, BC, A, P);
        radon_backproj_generic_kernel<<<(NN + 255) / 256, 256>>>(out, BC, A, P, N, NN);
    }
}